// round 12
// baseline (speedup 1.0000x reference)
#include <cuda_runtime.h>
#include <cuda_bf16.h>
#include <cstdint>

// ---------------------------------------------------------------------------
// LinkPredictorMLP restructured:
//   P split into 4 tables of [N,128] (51.2 MB each):
//     PR0 = emb @ W1[0:128, 0:128]     PR1 = emb @ W1[0:128, 128:256]
//     PC0 = emb @ W1[128:256, 0:128]   PC1 = emb @ W1[128:256, 128:256]
// edge pass k (k=0,1):  partial_k(e) = sum_{j in k-half} relu(PRk[row][j] +
//                       PCk[col][j] + b1[j+128k]) * W2[j+128k]
// out[e] = thresh(relu(partial_0 + partial_1 + b2))
// Each pass's gather working set = 102.4 MB -> fits L2.
//
// GEMM on mma.sync.m16n8k16 bf16 (fp32 accum), 2-term bf16 split
// (R8 champion config: BM=128, BN=128, BK=128, 3-pass loop, occ 1,
//  A-split fused into the tile load).
// ---------------------------------------------------------------------------

#define D_DIM   128
#define H_DIM   256
#define N_MAX   100000
#define E_MAX   600000
#define TAB     ((size_t)N_MAX * 128)

__device__ float          g_Pt[4 * TAB];                     // 204.8 MB total
__device__ float          g_partial[E_MAX];                  // 2.4 MB
__device__ __nv_bfloat16  g_Whi[(size_t)512 * D_DIM];        // Wt[j][k], 128 KB
__device__ __nv_bfloat16  g_Wlo[(size_t)512 * D_DIM];

static __device__ __forceinline__ uint32_t smem_u32(const void* p) {
    uint32_t a;
    asm("{ .reg .u64 t; cvta.to.shared.u64 t, %1; cvt.u32.u64 %0, t; }"
        : "=r"(a) : "l"(p));
    return a;
}

// ================= W conversion (transpose + bf16 split) ====================
// Output row j (0..511) maps: j<256 -> W1 top half col j ; j>=256 -> bottom.
// GEMM nblk n covers j in [n*128, n*128+128):
//   nblk0 = top,cols 0:128   (PR0)   nblk1 = top,cols 128:256   (PR1)
//   nblk2 = bot,cols 0:128   (PC0)   nblk3 = bot,cols 128:256   (PC1)

__global__ void __launch_bounds__(256)
conv_W_kernel(const float* __restrict__ W1) {
    int idx = blockIdx.x * 256 + threadIdx.x;   // 0..65535
    int j = idx >> 7;          // output column 0..511
    int k = idx & 127;         // input dim 0..127
    float w = (j < 256) ? W1[k * 256 + j] : W1[(128 + k) * 256 + (j - 256)];
    __nv_bfloat16 h = __float2bfloat16(w);
    __nv_bfloat16 l = __float2bfloat16(w - __bfloat162float(h));
    g_Whi[idx] = h;
    g_Wlo[idx] = l;
}

// ====================== mma.sync GEMM: P = emb @ Wcat =======================
// CTA: BM=128, BN=128, BK=128 resident. 8 warps, warp tile 64x32. occ 1.

#define SWZ_OFF(row, chunk) ((uint32_t)(row) * 256u + (uint32_t)(((chunk) ^ ((row) & 7)) << 4))

#define SM_A_HI 0
#define SM_A_LO 32768
#define SM_B_HI 65536
#define SM_B_LO 98304
#define SM_GEMM_TOTAL 131072

__device__ __forceinline__ void ldsm_x4(uint32_t addr, uint32_t& r0, uint32_t& r1,
                                        uint32_t& r2, uint32_t& r3) {
    asm volatile("ldmatrix.sync.aligned.m8n8.x4.shared.b16 {%0,%1,%2,%3}, [%4];"
                 : "=r"(r0), "=r"(r1), "=r"(r2), "=r"(r3) : "r"(addr));
}

__device__ __forceinline__ void mma16816(float& c0, float& c1, float& c2, float& c3,
                                         uint32_t a0, uint32_t a1, uint32_t a2, uint32_t a3,
                                         uint32_t b0, uint32_t b1) {
    asm volatile(
        "mma.sync.aligned.m16n8k16.row.col.f32.bf16.bf16.f32 "
        "{%0,%1,%2,%3}, {%4,%5,%6,%7}, {%8,%9}, {%0,%1,%2,%3};"
        : "+f"(c0), "+f"(c1), "+f"(c2), "+f"(c3)
        : "r"(a0), "r"(a1), "r"(a2), "r"(a3), "r"(b0), "r"(b1));
}

// split 4 fp32 -> packed bf16x2 hi pair + lo pair
__device__ __forceinline__ void split4(const float4& v, uint32_t& h01, uint32_t& h23,
                                       uint32_t& l01, uint32_t& l23) {
    __nv_bfloat16 h0 = __float2bfloat16(v.x), h1 = __float2bfloat16(v.y);
    __nv_bfloat16 h2 = __float2bfloat16(v.z), h3 = __float2bfloat16(v.w);
    __nv_bfloat16 l0 = __float2bfloat16(v.x - __bfloat162float(h0));
    __nv_bfloat16 l1 = __float2bfloat16(v.y - __bfloat162float(h1));
    __nv_bfloat16 l2 = __float2bfloat16(v.z - __bfloat162float(h2));
    __nv_bfloat16 l3 = __float2bfloat16(v.w - __bfloat162float(h3));
    __nv_bfloat162 hp0{h0, h1}, hp1{h2, h3}, lp0{l0, l1}, lp1{l2, l3};
    h01 = *(uint32_t*)&hp0; h23 = *(uint32_t*)&hp1;
    l01 = *(uint32_t*)&lp0; l23 = *(uint32_t*)&lp1;
}

__global__ void __launch_bounds__(256, 1)
gemm_kernel(const float* __restrict__ emb, int N) {
    extern __shared__ char smem[];
    const uint32_t sb = smem_u32(smem);

    const int tid  = threadIdx.x;
    const int wid  = tid >> 5;
    const int lane = tid & 31;
    const int nblk = blockIdx.x;              // 0..3 -> table index
    const int m0   = blockIdx.y * 128;

    // ---- load + split A tile: 128 rows x 16 chunks (8 floats each) ----
    #pragma unroll
    for (int i = tid; i < 2048; i += 256) {
        int row = i >> 4;
        int ch  = i & 15;
        int m = m0 + row;
        float4 v0, v1;
        if (m < N) {
            v0 = *(const float4*)(emb + (size_t)m * D_DIM + ch * 8);
            v1 = *(const float4*)(emb + (size_t)m * D_DIM + ch * 8 + 4);
        } else {
            v0 = make_float4(0.f, 0.f, 0.f, 0.f);
            v1 = v0;
        }
        uint4 hi, lo;
        split4(v0, hi.x, hi.y, lo.x, lo.y);
        split4(v1, hi.z, hi.w, lo.z, lo.w);
        uint32_t off = SWZ_OFF(row, ch);
        *(uint4*)(smem + SM_A_HI + off) = hi;
        *(uint4*)(smem + SM_A_LO + off) = lo;
    }
    // ---- load B tiles (hi+lo): 128 n-rows x 16 chunks of 16B ----
    const int jg0 = nblk * 128;
    #pragma unroll
    for (int i = tid; i < 2048; i += 256) {
        int row = i >> 4;
        int ch  = i & 15;
        uint4 vh = *(const uint4*)(g_Whi + (size_t)(jg0 + row) * D_DIM + ch * 8);
        uint4 vl = *(const uint4*)(g_Wlo + (size_t)(jg0 + row) * D_DIM + ch * 8);
        uint32_t off = SWZ_OFF(row, ch);
        *(uint4*)(smem + SM_B_HI + off) = vh;
        *(uint4*)(smem + SM_B_LO + off) = vl;
    }
    __syncthreads();

    const int wm = wid >> 2;                  // 0..1 -> row block of 64
    const int wn = wid & 3;                   // 0..3 -> col block of 32

    float c[4][4][4];
    #pragma unroll
    for (int mi = 0; mi < 4; mi++)
        #pragma unroll
        for (int ni = 0; ni < 4; ni++)
            #pragma unroll
            for (int q = 0; q < 4; q++)
                c[mi][ni][q] = 0.0f;

    const int a_row_l = lane & 15;
    const int a_kch_l = lane >> 4;
    const int b_row_l = (lane & 7) + ((lane >> 4) << 3);
    const int b_kch_l = (lane >> 3) & 1;

    const uint32_t abuf[3] = { sb + SM_A_HI, sb + SM_A_HI, sb + SM_A_LO };
    const uint32_t bbuf[3] = { sb + SM_B_HI, sb + SM_B_LO, sb + SM_B_HI };

    #pragma unroll
    for (int p = 0; p < 3; p++) {
        const uint32_t ab = abuf[p];
        const uint32_t bb = bbuf[p];
        #pragma unroll
        for (int ks = 0; ks < 8; ks++) {
            uint32_t a[4][4];
            #pragma unroll
            for (int mi = 0; mi < 4; mi++) {
                int row = wm * 64 + mi * 16 + a_row_l;
                ldsm_x4(ab + SWZ_OFF(row, 2 * ks + a_kch_l),
                        a[mi][0], a[mi][1], a[mi][2], a[mi][3]);
            }
            uint32_t b[4][2];
            #pragma unroll
            for (int np = 0; np < 2; np++) {
                int row = wn * 32 + np * 16 + b_row_l;
                uint32_t r0, r1, r2, r3;
                ldsm_x4(bb + SWZ_OFF(row, 2 * ks + b_kch_l), r0, r1, r2, r3);
                b[np * 2 + 0][0] = r0; b[np * 2 + 0][1] = r1;
                b[np * 2 + 1][0] = r2; b[np * 2 + 1][1] = r3;
            }
            #pragma unroll
            for (int mi = 0; mi < 4; mi++)
                #pragma unroll
                for (int ni = 0; ni < 4; ni++)
                    mma16816(c[mi][ni][0], c[mi][ni][1], c[mi][ni][2], c[mi][ni][3],
                             a[mi][0], a[mi][1], a[mi][2], a[mi][3],
                             b[ni][0], b[ni][1]);
        }
    }

    // ---- epilogue: each nblk writes its own [N,128] table ----
    float* dst = g_Pt + (size_t)nblk * TAB;
    const int qrow = lane >> 2;
    const int qcol = (lane & 3) * 2;
    const int colbase = wn * 32;
    #pragma unroll
    for (int mi = 0; mi < 4; mi++) {
        int r0 = m0 + wm * 64 + mi * 16 + qrow;
        #pragma unroll
        for (int ni = 0; ni < 4; ni++) {
            int cc = colbase + ni * 8 + qcol;
            if (r0 < N)
                *(float2*)(dst + (size_t)r0 * 128 + cc) =
                    make_float2(c[mi][ni][0], c[mi][ni][1]);
            if (r0 + 8 < N)
                *(float2*)(dst + (size_t)(r0 + 8) * 128 + cc) =
                    make_float2(c[mi][ni][2], c[mi][ni][3]);
        }
    }
}

// ========================= Kernel: edge pass ================================
// One warp per edge; each lane handles one float4 (4 hidden units) of the
// 128-unit half. phase 0 gathers PR0/PC0 (102 MB, L2-resident), writes
// partial; phase 1 gathers PR1/PC1, adds partial, thresholds, writes out.

template <int PHASE>
__global__ void __launch_bounds__(256)
edge_pass_kernel(const int* __restrict__ eidx,
                 const float* __restrict__ b1,
                 const float* __restrict__ W2,
                 const float* __restrict__ b2,
                 float* __restrict__ out,
                 int E) {
    __shared__ float s_b1[128];
    __shared__ float s_w2[128];

    const int tid = threadIdx.x;
    if (tid < 128) {
        s_b1[tid] = b1[PHASE * 128 + tid];
        s_w2[tid] = W2[PHASE * 128 + tid];
    }
    __syncthreads();

    const int warp = tid >> 5;
    const int lane = tid & 31;
    const int e = blockIdx.x * 8 + warp;
    if (e >= E) return;

    const int row = __ldg(&eidx[e]);
    const int col = __ldg(&eidx[E + e]);

    const float4* __restrict__ Ap  = (const float4*)(g_Pt + (size_t)(0 + PHASE) * TAB
                                                     + (size_t)row * 128);
    const float4* __restrict__ Bp  = (const float4*)(g_Pt + (size_t)(2 + PHASE) * TAB
                                                     + (size_t)col * 128);
    const float4* __restrict__ b1v = (const float4*)s_b1;
    const float4* __restrict__ w2v = (const float4*)s_w2;

    float4 a  = Ap[lane];
    float4 b  = Bp[lane];
    float4 bi = b1v[lane];
    float4 w  = w2v[lane];
    float h0 = fmaxf(a.x + b.x + bi.x, 0.0f);
    float h1 = fmaxf(a.y + b.y + bi.y, 0.0f);
    float h2 = fmaxf(a.z + b.z + bi.z, 0.0f);
    float h3 = fmaxf(a.w + b.w + bi.w, 0.0f);
    float acc = h0 * w.x;
    acc = fmaf(h1, w.y, acc);
    acc = fmaf(h2, w.z, acc);
    acc = fmaf(h3, w.w, acc);

    #pragma unroll
    for (int off = 16; off > 0; off >>= 1)
        acc += __shfl_xor_sync(0xFFFFFFFFu, acc, off);

    if (lane == 0) {
        if (PHASE == 0) {
            g_partial[e] = acc;
        } else {
            float raw = acc + g_partial[e] + __ldg(b2);
            float w = fmaxf(raw, 0.0f);
            out[e] = (w < 0.05f) ? 0.0f : w;
        }
    }
}

// ============================== launcher ====================================

extern "C" void kernel_launch(void* const* d_in, const int* in_sizes, int n_in,
                              void* d_out, int out_size) {
    const float* emb = (const float*)d_in[0];
    const int*   eix = (const int*)d_in[1];
    const float* W1  = (const float*)d_in[2];
    const float* b1  = (const float*)d_in[3];
    const float* W2  = (const float*)d_in[4];
    const float* b2  = (const float*)d_in[5];
    float*       out = (float*)d_out;

    const int N = in_sizes[0] / D_DIM;     // 100000
    const int E = in_sizes[1] / 2;         // 600000

    cudaFuncSetAttribute(gemm_kernel,
                         cudaFuncAttributeMaxDynamicSharedMemorySize, SM_GEMM_TOTAL);

    conv_W_kernel<<<(512 * D_DIM) / 256, 256>>>(W1);

    dim3 grid1(4, (N + 127) / 128);        // (4, 782)
    gemm_kernel<<<grid1, 256, SM_GEMM_TOTAL>>>(emb, N);

    int blocks2 = (E + 7) / 8;
    edge_pass_kernel<0><<<blocks2, 256>>>(eix, b1, W2, b2, out, E);
    edge_pass_kernel<1><<<blocks2, 256>>>(eix, b1, W2, b2, out, E);
}

// round 13
// speedup vs baseline: 1.3386x; 1.3386x over previous
#include <cuda_runtime.h>
#include <cuda_bf16.h>
#include <cstdint>

// ---------------------------------------------------------------------------
// LinkPredictorMLP restructured:
//   P split into 4 tables of [N,128] (51.2 MB each):
//     PR0 = emb @ W1[0:128, 0:128]     PR1 = emb @ W1[0:128, 128:256]
//     PC0 = emb @ W1[128:256, 0:128]   PC1 = emb @ W1[128:256, 128:256]
// edge pass k (k=0,1):  partial_k(e) = sum_{j in k-half} relu(PRk[row][j] +
//                       PCk[col][j] + b1[j+128k]) * W2[j+128k]
// out[e] = thresh(relu(partial_0 + partial_1 + b2))
// Each pass's gather working set = 102.4 MB -> fits L2 (proven: DRAM 24%).
// R12: pass kernels reworked — no smem/sync preamble, 4 edges/warp with
// batched gathers (MLP 8/lane), b1/W2 via L1-resident __ldg.
//
// GEMM on mma.sync.m16n8k16 bf16 (fp32 accum), 2-term bf16 split
// (R8 champion config: BM=128, BN=128, BK=128, 3-pass loop, occ 1).
// ---------------------------------------------------------------------------

#define D_DIM   128
#define H_DIM   256
#define N_MAX   100000
#define E_MAX   600000
#define TAB     ((size_t)N_MAX * 128)

__device__ float          g_Pt[4 * TAB];                     // 204.8 MB total
__device__ float          g_partial[E_MAX];                  // 2.4 MB
__device__ __nv_bfloat16  g_Whi[(size_t)512 * D_DIM];        // Wt[j][k], 128 KB
__device__ __nv_bfloat16  g_Wlo[(size_t)512 * D_DIM];

static __device__ __forceinline__ uint32_t smem_u32(const void* p) {
    uint32_t a;
    asm("{ .reg .u64 t; cvta.to.shared.u64 t, %1; cvt.u32.u64 %0, t; }"
        : "=r"(a) : "l"(p));
    return a;
}

// ================= W conversion (transpose + bf16 split) ====================

__global__ void __launch_bounds__(256)
conv_W_kernel(const float* __restrict__ W1) {
    int idx = blockIdx.x * 256 + threadIdx.x;   // 0..65535
    int j = idx >> 7;          // output column 0..511
    int k = idx & 127;         // input dim 0..127
    float w = (j < 256) ? W1[k * 256 + j] : W1[(128 + k) * 256 + (j - 256)];
    __nv_bfloat16 h = __float2bfloat16(w);
    __nv_bfloat16 l = __float2bfloat16(w - __bfloat162float(h));
    g_Whi[idx] = h;
    g_Wlo[idx] = l;
}

// ====================== mma.sync GEMM: P = emb @ Wcat =======================
// CTA: BM=128, BN=128, BK=128 resident. 8 warps, warp tile 64x32. occ 1.

#define SWZ_OFF(row, chunk) ((uint32_t)(row) * 256u + (uint32_t)(((chunk) ^ ((row) & 7)) << 4))

#define SM_A_HI 0
#define SM_A_LO 32768
#define SM_B_HI 65536
#define SM_B_LO 98304
#define SM_GEMM_TOTAL 131072

__device__ __forceinline__ void ldsm_x4(uint32_t addr, uint32_t& r0, uint32_t& r1,
                                        uint32_t& r2, uint32_t& r3) {
    asm volatile("ldmatrix.sync.aligned.m8n8.x4.shared.b16 {%0,%1,%2,%3}, [%4];"
                 : "=r"(r0), "=r"(r1), "=r"(r2), "=r"(r3) : "r"(addr));
}

__device__ __forceinline__ void mma16816(float& c0, float& c1, float& c2, float& c3,
                                         uint32_t a0, uint32_t a1, uint32_t a2, uint32_t a3,
                                         uint32_t b0, uint32_t b1) {
    asm volatile(
        "mma.sync.aligned.m16n8k16.row.col.f32.bf16.bf16.f32 "
        "{%0,%1,%2,%3}, {%4,%5,%6,%7}, {%8,%9}, {%0,%1,%2,%3};"
        : "+f"(c0), "+f"(c1), "+f"(c2), "+f"(c3)
        : "r"(a0), "r"(a1), "r"(a2), "r"(a3), "r"(b0), "r"(b1));
}

// split 4 fp32 -> packed bf16x2 hi pair + lo pair
__device__ __forceinline__ void split4(const float4& v, uint32_t& h01, uint32_t& h23,
                                       uint32_t& l01, uint32_t& l23) {
    __nv_bfloat16 h0 = __float2bfloat16(v.x), h1 = __float2bfloat16(v.y);
    __nv_bfloat16 h2 = __float2bfloat16(v.z), h3 = __float2bfloat16(v.w);
    __nv_bfloat16 l0 = __float2bfloat16(v.x - __bfloat162float(h0));
    __nv_bfloat16 l1 = __float2bfloat16(v.y - __bfloat162float(h1));
    __nv_bfloat16 l2 = __float2bfloat16(v.z - __bfloat162float(h2));
    __nv_bfloat16 l3 = __float2bfloat16(v.w - __bfloat162float(h3));
    __nv_bfloat162 hp0{h0, h1}, hp1{h2, h3}, lp0{l0, l1}, lp1{l2, l3};
    h01 = *(uint32_t*)&hp0; h23 = *(uint32_t*)&hp1;
    l01 = *(uint32_t*)&lp0; l23 = *(uint32_t*)&lp1;
}

__global__ void __launch_bounds__(256, 1)
gemm_kernel(const float* __restrict__ emb, int N) {
    extern __shared__ char smem[];
    const uint32_t sb = smem_u32(smem);

    const int tid  = threadIdx.x;
    const int wid  = tid >> 5;
    const int lane = tid & 31;
    const int nblk = blockIdx.x;              // 0..3 -> table index
    const int m0   = blockIdx.y * 128;

    // ---- load + split A tile: 128 rows x 16 chunks (8 floats each) ----
    #pragma unroll
    for (int i = tid; i < 2048; i += 256) {
        int row = i >> 4;
        int ch  = i & 15;
        int m = m0 + row;
        float4 v0, v1;
        if (m < N) {
            v0 = *(const float4*)(emb + (size_t)m * D_DIM + ch * 8);
            v1 = *(const float4*)(emb + (size_t)m * D_DIM + ch * 8 + 4);
        } else {
            v0 = make_float4(0.f, 0.f, 0.f, 0.f);
            v1 = v0;
        }
        uint4 hi, lo;
        split4(v0, hi.x, hi.y, lo.x, lo.y);
        split4(v1, hi.z, hi.w, lo.z, lo.w);
        uint32_t off = SWZ_OFF(row, ch);
        *(uint4*)(smem + SM_A_HI + off) = hi;
        *(uint4*)(smem + SM_A_LO + off) = lo;
    }
    // ---- load B tiles (hi+lo): 128 n-rows x 16 chunks of 16B ----
    const int jg0 = nblk * 128;
    #pragma unroll
    for (int i = tid; i < 2048; i += 256) {
        int row = i >> 4;
        int ch  = i & 15;
        uint4 vh = *(const uint4*)(g_Whi + (size_t)(jg0 + row) * D_DIM + ch * 8);
        uint4 vl = *(const uint4*)(g_Wlo + (size_t)(jg0 + row) * D_DIM + ch * 8);
        uint32_t off = SWZ_OFF(row, ch);
        *(uint4*)(smem + SM_B_HI + off) = vh;
        *(uint4*)(smem + SM_B_LO + off) = vl;
    }
    __syncthreads();

    const int wm = wid >> 2;                  // 0..1 -> row block of 64
    const int wn = wid & 3;                   // 0..3 -> col block of 32

    float c[4][4][4];
    #pragma unroll
    for (int mi = 0; mi < 4; mi++)
        #pragma unroll
        for (int ni = 0; ni < 4; ni++)
            #pragma unroll
            for (int q = 0; q < 4; q++)
                c[mi][ni][q] = 0.0f;

    const int a_row_l = lane & 15;
    const int a_kch_l = lane >> 4;
    const int b_row_l = (lane & 7) + ((lane >> 4) << 3);
    const int b_kch_l = (lane >> 3) & 1;

    const uint32_t abuf[3] = { sb + SM_A_HI, sb + SM_A_HI, sb + SM_A_LO };
    const uint32_t bbuf[3] = { sb + SM_B_HI, sb + SM_B_LO, sb + SM_B_HI };

    #pragma unroll
    for (int p = 0; p < 3; p++) {
        const uint32_t ab = abuf[p];
        const uint32_t bb = bbuf[p];
        #pragma unroll
        for (int ks = 0; ks < 8; ks++) {
            uint32_t a[4][4];
            #pragma unroll
            for (int mi = 0; mi < 4; mi++) {
                int row = wm * 64 + mi * 16 + a_row_l;
                ldsm_x4(ab + SWZ_OFF(row, 2 * ks + a_kch_l),
                        a[mi][0], a[mi][1], a[mi][2], a[mi][3]);
            }
            uint32_t b[4][2];
            #pragma unroll
            for (int np = 0; np < 2; np++) {
                int row = wn * 32 + np * 16 + b_row_l;
                uint32_t r0, r1, r2, r3;
                ldsm_x4(bb + SWZ_OFF(row, 2 * ks + b_kch_l), r0, r1, r2, r3);
                b[np * 2 + 0][0] = r0; b[np * 2 + 0][1] = r1;
                b[np * 2 + 1][0] = r2; b[np * 2 + 1][1] = r3;
            }
            #pragma unroll
            for (int mi = 0; mi < 4; mi++)
                #pragma unroll
                for (int ni = 0; ni < 4; ni++)
                    mma16816(c[mi][ni][0], c[mi][ni][1], c[mi][ni][2], c[mi][ni][3],
                             a[mi][0], a[mi][1], a[mi][2], a[mi][3],
                             b[ni][0], b[ni][1]);
        }
    }

    // ---- epilogue: each nblk writes its own [N,128] table ----
    float* dst = g_Pt + (size_t)nblk * TAB;
    const int qrow = lane >> 2;
    const int qcol = (lane & 3) * 2;
    const int colbase = wn * 32;
    #pragma unroll
    for (int mi = 0; mi < 4; mi++) {
        int r0 = m0 + wm * 64 + mi * 16 + qrow;
        #pragma unroll
        for (int ni = 0; ni < 4; ni++) {
            int cc = colbase + ni * 8 + qcol;
            if (r0 < N)
                *(float2*)(dst + (size_t)r0 * 128 + cc) =
                    make_float2(c[mi][ni][0], c[mi][ni][1]);
            if (r0 + 8 < N)
                *(float2*)(dst + (size_t)(r0 + 8) * 128 + cc) =
                    make_float2(c[mi][ni][2], c[mi][ni][3]);
        }
    }
}

// ========================= Kernel: edge pass ================================
// 4 edges per warp; lane owns float4 column `lane` of the 128-unit half.
// All 8 gathers issued back-to-back (MLP 8/lane). No smem, no syncs; b1/W2
// float4s live in L1 (4 KB working set).

template <int PHASE>
__global__ void __launch_bounds__(256)
edge_pass_kernel(const int* __restrict__ eidx,
                 const float* __restrict__ b1,
                 const float* __restrict__ W2,
                 const float* __restrict__ b2,
                 float* __restrict__ out,
                 int E) {
    const int lane   = threadIdx.x & 31;
    const int warp_g = (blockIdx.x * 256 + threadIdx.x) >> 5;
    const int e0 = warp_g * 4;
    if (e0 >= E) return;

    const float* __restrict__ PR = g_Pt + (size_t)(0 + PHASE) * TAB;
    const float* __restrict__ PC = g_Pt + (size_t)(2 + PHASE) * TAB;

    const float4 bi = __ldg((const float4*)(b1 + PHASE * 128) + lane);
    const float4 w  = __ldg((const float4*)(W2 + PHASE * 128) + lane);

    // ---- batch: indices for 4 edges ----
    int rows[4], cols[4];
    #pragma unroll
    for (int i = 0; i < 4; i++) {
        int e = e0 + i;
        int ec = (e < E) ? e : (E - 1);
        rows[i] = __ldg(&eidx[ec]);
        cols[i] = __ldg(&eidx[E + ec]);
    }
    // ---- batch: 8 gathers in flight ----
    float4 av[4], bv[4];
    #pragma unroll
    for (int i = 0; i < 4; i++) {
        av[i] = __ldg((const float4*)(PR + (size_t)rows[i] * 128) + lane);
        bv[i] = __ldg((const float4*)(PC + (size_t)cols[i] * 128) + lane);
    }
    // ---- compute + reduce per edge ----
    #pragma unroll
    for (int i = 0; i < 4; i++) {
        int e = e0 + i;
        float h0 = fmaxf(av[i].x + bv[i].x + bi.x, 0.0f);
        float h1 = fmaxf(av[i].y + bv[i].y + bi.y, 0.0f);
        float h2 = fmaxf(av[i].z + bv[i].z + bi.z, 0.0f);
        float h3 = fmaxf(av[i].w + bv[i].w + bi.w, 0.0f);
        float acc = h0 * w.x;
        acc = fmaf(h1, w.y, acc);
        acc = fmaf(h2, w.z, acc);
        acc = fmaf(h3, w.w, acc);
        #pragma unroll
        for (int off = 16; off > 0; off >>= 1)
            acc += __shfl_xor_sync(0xFFFFFFFFu, acc, off);
        if (lane == 0 && e < E) {
            if (PHASE == 0) {
                g_partial[e] = acc;
            } else {
                float raw = acc + g_partial[e] + __ldg(b2);
                float ww = fmaxf(raw, 0.0f);
                out[e] = (ww < 0.05f) ? 0.0f : ww;
            }
        }
    }
}

// ============================== launcher ====================================

extern "C" void kernel_launch(void* const* d_in, const int* in_sizes, int n_in,
                              void* d_out, int out_size) {
    const float* emb = (const float*)d_in[0];
    const int*   eix = (const int*)d_in[1];
    const float* W1  = (const float*)d_in[2];
    const float* b1  = (const float*)d_in[3];
    const float* W2  = (const float*)d_in[4];
    const float* b2  = (const float*)d_in[5];
    float*       out = (float*)d_out;

    const int N = in_sizes[0] / D_DIM;     // 100000
    const int E = in_sizes[1] / 2;         // 600000

    cudaFuncSetAttribute(gemm_kernel,
                         cudaFuncAttributeMaxDynamicSharedMemorySize, SM_GEMM_TOTAL);

    conv_W_kernel<<<(512 * D_DIM) / 256, 256>>>(W1);

    dim3 grid1(4, (N + 127) / 128);        // (4, 782)
    gemm_kernel<<<grid1, 256, SM_GEMM_TOTAL>>>(emb, N);

    // 4 edges per warp, 8 warps per block -> 32 edges per block
    int blocks2 = (E + 31) / 32;           // 18750
    edge_pass_kernel<0><<<blocks2, 256>>>(eix, b1, W2, b2, out, E);
    edge_pass_kernel<1><<<blocks2, 256>>>(eix, b1, W2, b2, out, E);
}